// round 16
// baseline (speedup 1.0000x reference)
#include <cuda_runtime.h>
#include <cuda_bf16.h>
#include <stdint.h>
#include <math.h>

// ---------- problem constants ----------
#define NROWS    131072           // 512 graphs * 256 nodes
#define INDIM    128
#define HIDN     128
#define D2       256
#define MTILE    32               // rows per CTA
#define NCTA     (NROWS / MTILE)  // 4096
#define NTHREADS 256              // 8 warps, each 32 rows x 32 cols

// ---------- smem layout (bytes) ----------
#define SM_AHI   0                // 16KB A hi  (32 rows x 256 k bf16)
#define SM_ALO   16384            // 16KB A lo
#define SM_BW    32768            // per-warp B rings: 8 warps x 8KB (4 bufs x (hi 1KB | lo 1KB))
#define SM_EMB   98304            // 128 f32
#define SM_B1    98816            // 256 f32
#define SM_B2    99840            // 256 f32
#define SM_W3    100864           // 512 f32
#define SM_RED   102912           // 8*32*2 f32 = 2KB
#define SM_TOTAL 104960           // <= 113664 for 2 CTAs/SM

// B fragments in global scratch, coalesced layout (same as R7..R15):
// u32 idx = ((((l*2+p)*16 + ks)*4 + wn)*4 + q)*128 + lane*4 + j
__device__ uint32_t g_Bf[131072];   // 512KB

static __device__ __forceinline__ uint32_t pack_bf(__nv_bfloat16 a, __nv_bfloat16 b) {
    return ((uint32_t)__bfloat16_as_ushort(b) << 16) | (uint32_t)__bfloat16_as_ushort(a);
}
static __device__ __forceinline__ void split_bf(float v, __nv_bfloat16& hi, __nv_bfloat16& lo) {
    hi = __float2bfloat16(v);
    lo = __float2bfloat16(v - __bfloat162float(hi));
}
static __device__ __forceinline__ uint32_t s2u(const void* p) {
    uint32_t a;
    asm("{ .reg .u64 t; cvta.to.shared.u64 t, %1; cvt.u32.u64 %0, t; }"
        : "=r"(a) : "l"(p));
    return a;
}
// fast accurate tanh: 1 - 2/(2^(x*2*log2e) + 1); MUFU.EX2 + MUFU.RCP
static __device__ __forceinline__ float fast_tanh(float x) {
    float e, r;
    asm("ex2.approx.f32 %0, %1;" : "=f"(e) : "f"(x * 2.8853900817779268f));
    asm("rcp.approx.f32 %0, %1;" : "=f"(r) : "f"(e + 1.0f));
    return fmaf(-2.0f, r, 1.0f);
}
// truncation split: hi-pair via PRMT, lo-pair via rn(v - hi)
static __device__ __forceinline__ uint32_t pack_hi_trunc(float a, float b) {
    uint32_t r;
    asm("prmt.b32 %0, %1, %2, 0x7632;" : "=r"(r)
        : "r"(__float_as_uint(a)), "r"(__float_as_uint(b)));
    return r;
}
static __device__ __forceinline__ float trunc_hi(float v) {
    return __uint_as_float(__float_as_uint(v) & 0xffff0000u);
}
static __device__ __forceinline__ uint32_t pack_lo(float a, float b) {
    uint32_t r;
    float la = a - trunc_hi(a);
    float lb = b - trunc_hi(b);
    asm("cvt.rn.bf16x2.f32 %0, %1, %2;" : "=r"(r) : "f"(lb), "f"(la));
    return r;
}

// ---------- prep: split W1/W2 into bf16 hi/lo fragments (coalesced layout) ----------
__global__ void prep_weights(const float* __restrict__ W1, const float* __restrict__ W2) {
    int i = blockIdx.x * blockDim.x + threadIdx.x;   // 0..131071
    int j    = i & 3;
    int lane = (i >> 2) & 31;
    int q    = (i >> 7) & 3;
    int wn   = (i >> 9) & 3;
    int ks   = (i >> 11) & 15;
    int p    = (i >> 15) & 1;
    int l    = i >> 16;
    int s   = q * 4 + j;
    int nt  = s >> 1;
    int reg = s & 1;
    int NT  = wn * 8 + nt;
    const float* W = l ? W2 : W1;
    int k0 = ks * 16 + (lane & 3) * 2 + reg * 8;
    int n  = NT * 8 + (lane >> 2);
    float v0 = W[k0 * 256 + n];
    float v1 = W[(k0 + 1) * 256 + n];
    __nv_bfloat16 h0, l0, h1, l1;
    split_bf(v0, h0, l0);
    split_bf(v1, h1, l1);
    g_Bf[i] = (p == 0) ? pack_bf(h0, h1) : pack_bf(l0, l1);
}

// ---------- asm wrappers ----------
static __device__ __forceinline__ void mma_bf16(float* d, const uint32_t* a,
                                                uint32_t b0, uint32_t b1) {
    asm volatile(
        "mma.sync.aligned.m16n8k16.row.col.f32.bf16.bf16.f32 "
        "{%0,%1,%2,%3}, {%4,%5,%6,%7}, {%8,%9}, {%0,%1,%2,%3};"
        : "+f"(d[0]), "+f"(d[1]), "+f"(d[2]), "+f"(d[3])
        : "r"(a[0]), "r"(a[1]), "r"(a[2]), "r"(a[3]), "r"(b0), "r"(b1));
}
static __device__ __forceinline__ void ldsm4(uint32_t* r, uint32_t saddr) {
    asm volatile("ldmatrix.sync.aligned.m8n8.x4.shared.b16 {%0,%1,%2,%3}, [%4];"
                 : "=r"(r[0]), "=r"(r[1]), "=r"(r[2]), "=r"(r[3]) : "r"(saddr));
}
static __device__ __forceinline__ void lds128(uint4& v, uint32_t saddr) {
    asm volatile("ld.shared.v4.u32 {%0,%1,%2,%3}, [%4];"
                 : "=r"(v.x), "=r"(v.y), "=r"(v.z), "=r"(v.w) : "r"(saddr));
}
static __device__ __forceinline__ void cp16(uint32_t dst, const void* src) {
    asm volatile("cp.async.cg.shared.global [%0], [%1], 16;"
                 :: "r"(dst), "l"(src) : "memory");
}
#define CP_COMMIT() asm volatile("cp.async.commit_group;" ::: "memory")
#define CP_WAIT(n)  asm volatile("cp.async.wait_group %0;" :: "n"(n) : "memory")

// A smem byte offset for (row r 0..31, k); k-halves (16B) swapped when r&4.
// per-ks block = 32 rows * 32B = 1KB
static __device__ __forceinline__ uint32_t offA(int r, int k) {
    uint32_t c = (uint32_t)(k & 15);
    uint32_t cp = (c + (uint32_t)((r & 4) << 1)) & 15u;
    return ((uint32_t)(k >> 4) << 10) + ((uint32_t)r << 5) + (cp << 1);
}

// ---------- main fused kernel ----------
__global__ __launch_bounds__(NTHREADS, 2)
void fused_hmma_kernel(const float* __restrict__ last,
                       const float* __restrict__ h,
                       const float* __restrict__ We,
                       const float* __restrict__ be,
                       const float* __restrict__ b1,
                       const float* __restrict__ b2,
                       const float* __restrict__ W3,
                       const float* __restrict__ b3,
                       float* __restrict__ out) {
    extern __shared__ char sm[];
    const uint32_t smb = s2u(sm);
    const int tid  = threadIdx.x;
    const int lane = tid & 31;
    const int wn2  = tid >> 5;       // warp id = 32-col slice, 0..7
    const int r0   = blockIdx.x * MTILE;
    const int grp  = r0 >> 8;

    float* sEmb = (float*)(sm + SM_EMB);
    float* sB1  = (float*)(sm + SM_B1);
    float* sB2  = (float*)(sm + SM_B2);
    float* sW3  = (float*)(sm + SM_W3);
    float* sRed = (float*)(sm + SM_RED);

    // per-warp B ring: warp slice of global ks-block = [wn2*1KB, +1KB)
    const uint32_t bufbase = smb + SM_BW + (uint32_t)wn2 * 8192 + (uint32_t)lane * 16;
    const uint32_t gwoff   = (uint32_t)wn2 * 256 + (uint32_t)lane * 4;   // u32 units

    // per-warp fetch of global ks index ksg (0..31; layer = ksg>>4) into ring slot ksg&3
    auto fetchB = [&](int ksg) {
        const uint32_t* srcH = g_Bf + (uint32_t)(((ksg >> 4) * 32 + (ksg & 15)) * 2048) + gwoff;
        uint32_t dst = bufbase + (uint32_t)(ksg & 3) * 2048;
        cp16(dst,         srcH);
        cp16(dst + 512,   srcH + 128);
        cp16(dst + 1024,  srcH + 32768);        // lo part (p=1): +16*2048 u32
        cp16(dst + 1536,  srcH + 32768 + 128);
        CP_COMMIT();
    };

    // ---- prologue: 4-deep per-warp prefetch, overlaps A build ----
    fetchB(0); fetchB(1); fetchB(2); fetchB(3);

    sB1[tid] = b1[tid];
    sB2[tid] = b2[tid];
    sW3[tid]       = W3[tid];
    sW3[tid + 256] = W3[tid + 256];

    if (tid < HIDN) {
        float acc0 = be[tid];
        const float* lrow = last + (size_t)grp * INDIM;
        #pragma unroll 4
        for (int k = 0; k < INDIM; k++)
            acc0 = fmaf(lrow[k], We[k * HIDN + tid], acc0);
        sEmb[tid] = acc0;
    }

    // A tile, h half: 32 rows x 128 k
    #pragma unroll
    for (int it = 0; it < 4; it++) {
        int idx = tid + it * NTHREADS;
        int r = idx >> 5, kq = idx & 31, k = kq * 4;
        float4 v = *(const float4*)(h + (size_t)(r0 + r) * HIDN + k);
        uint32_t off = offA(r, k);
        *(uint2*)(sm + SM_AHI + off) = make_uint2(pack_hi_trunc(v.x, v.y), pack_hi_trunc(v.z, v.w));
        *(uint2*)(sm + SM_ALO + off) = make_uint2(pack_lo(v.x, v.y),       pack_lo(v.z, v.w));
    }
    __syncthreads();   // sEmb ready

    // A tile, embed half: k 128..255, broadcast across rows
    #pragma unroll
    for (int it = 0; it < 4; it++) {
        int idx = tid + it * NTHREADS;
        int r = idx >> 5, kq = idx & 31, k = 128 + kq * 4;
        float4 v = *(const float4*)(sEmb + kq * 4);
        uint32_t off = offA(r, k);
        *(uint2*)(sm + SM_AHI + off) = make_uint2(pack_hi_trunc(v.x, v.y), pack_hi_trunc(v.z, v.w));
        *(uint2*)(sm + SM_ALO + off) = make_uint2(pack_lo(v.x, v.y),       pack_lo(v.z, v.w));
    }
    __syncthreads();   // A tile complete before any warp's mainloop reads

    const int g   = lane >> 2;
    const int tig = lane & 3;

    // per-lane ldmatrix offset within a 16-row block
    uint32_t laneoff;
    {
        int q = lane >> 3, rr = lane & 7;
        laneoff = (uint32_t)(((q & 1) * 8 + rr) * 32 +
                             ((((q >> 1) ^ (rr >> 2)) & 1) << 4));
    }
    const uint32_t abm0 = laneoff;          // rows 0..15
    const uint32_t abm1 = 512 + laneoff;    // rows 16..31

    // register-double-buffered fragments
    uint32_t BH[2][8], BL[2][8];
    uint32_t AH[2][2][4], AL[2][2][4];
    float acc[2][4][4];

    auto loadB = [&](int ksg, int buf) {
        uint32_t bb = bufbase + (uint32_t)(ksg & 3) * 2048;
        uint4 t0, t1, t2, t3;
        lds128(t0, bb);
        lds128(t1, bb + 512);
        lds128(t2, bb + 1024);
        lds128(t3, bb + 1536);
        BH[buf][0] = t0.x; BH[buf][1] = t0.y; BH[buf][2] = t0.z; BH[buf][3] = t0.w;
        BH[buf][4] = t1.x; BH[buf][5] = t1.y; BH[buf][6] = t1.z; BH[buf][7] = t1.w;
        BL[buf][0] = t2.x; BL[buf][1] = t2.y; BL[buf][2] = t2.z; BL[buf][3] = t2.w;
        BL[buf][4] = t3.x; BL[buf][5] = t3.y; BL[buf][6] = t3.z; BL[buf][7] = t3.w;
    };
    auto loadA = [&](int ksg, int buf) {
        uint32_t ab = smb + SM_AHI + ((uint32_t)(ksg & 15) << 10);
        ldsm4(AH[buf][0], ab + abm0);
        ldsm4(AH[buf][1], ab + abm1);
        ldsm4(AL[buf][0], ab + 16384 + abm0);
        ldsm4(AL[buf][1], ab + 16384 + abm1);
    };

    // ---- prologue of pipeline: frags(0) ----
    CP_WAIT(3);          // group 0 retired (groups 1..3 pending)
    loadB(0, 0);
    loadA(0, 0);

    // ---- software-pipelined barrier-free mainloop: 32 global ks ----
    #pragma unroll 2
    for (int ksg = 0; ksg < 32; ksg++) {
        const int cur = ksg & 1, nxt = cur ^ 1;

        if ((ksg & 15) == 0) {
            #pragma unroll
            for (int mt = 0; mt < 2; mt++)
                #pragma unroll
                for (int nt = 0; nt < 4; nt++)
                    #pragma unroll
                    for (int c = 0; c < 4; c++)
                        acc[mt][nt][c] = 0.f;
        }

        // preload frags(ksg+1) before this iteration's MMAs
        if (ksg < 31) {
            if (ksg < 29)      { CP_WAIT(2); }   // groups <= ksg+1 retired
            else if (ksg == 29){ CP_WAIT(1); }
            else               { CP_WAIT(0); }
            if (ksg <= 27) fetchB(ksg + 4);      // refill ring slot (ksg)&3 (already consumed)
            loadB(ksg + 1, nxt);
            if (ksg != 15) loadA(ksg + 1, nxt);  // A rewritten at layer boundary
        }

        // MMAs for ksg from registers
        #pragma unroll
        for (int mt = 0; mt < 2; mt++)
            #pragma unroll
            for (int nt = 0; nt < 4; nt++)
                mma_bf16(acc[mt][nt], AH[cur][mt], BH[cur][nt * 2], BH[cur][nt * 2 + 1]);
        #pragma unroll
        for (int mt = 0; mt < 2; mt++)
            #pragma unroll
            for (int nt = 0; nt < 4; nt++)
                mma_bf16(acc[mt][nt], AH[cur][mt], BL[cur][nt * 2], BL[cur][nt * 2 + 1]);
        #pragma unroll
        for (int mt = 0; mt < 2; mt++)
            #pragma unroll
            for (int nt = 0; nt < 4; nt++)
                mma_bf16(acc[mt][nt], AL[cur][mt], BH[cur][nt * 2], BH[cur][nt * 2 + 1]);

        if (ksg == 15) {
            // ===== layer boundary: the ONLY CTA barriers in the mainloop =====
            __syncthreads();   // all warps done reading layer-1 A
            #pragma unroll
            for (int mt = 0; mt < 2; mt++) {
                int rA = mt * 16 + g;
                int rB = rA + 8;
                #pragma unroll
                for (int nt = 0; nt < 4; nt++) {
                    int c0 = wn2 * 32 + nt * 8 + tig * 2;
                    float t0 = fast_tanh(acc[mt][nt][0] + sB1[c0]);
                    float t1 = fast_tanh(acc[mt][nt][1] + sB1[c0 + 1]);
                    float t2 = fast_tanh(acc[mt][nt][2] + sB1[c0]);
                    float t3 = fast_tanh(acc[mt][nt][3] + sB1[c0 + 1]);
                    uint32_t oA = offA(rA, c0);
                    *(uint32_t*)(sm + SM_AHI + oA) = pack_hi_trunc(t0, t1);
                    *(uint32_t*)(sm + SM_ALO + oA) = pack_lo(t0, t1);
                    uint32_t oB = offA(rB, c0);
                    *(uint32_t*)(sm + SM_AHI + oB) = pack_hi_trunc(t2, t3);
                    *(uint32_t*)(sm + SM_ALO + oB) = pack_lo(t2, t3);
                }
            }
            __syncthreads();   // layer-2 A visible to all warps
            loadA(16, nxt);    // complete the preload for ksg=16
        }
    }

    // ===== epilogue 2: tanh(+b2), dot with W3, reduce =====
    float e[2][2][2];   // [mt][rowhalf][comp]
    #pragma unroll
    for (int mt = 0; mt < 2; mt++)
        #pragma unroll
        for (int hh = 0; hh < 2; hh++) { e[mt][hh][0] = 0.f; e[mt][hh][1] = 0.f; }

    #pragma unroll
    for (int mt = 0; mt < 2; mt++)
        #pragma unroll
        for (int nt = 0; nt < 4; nt++) {
            int c0 = wn2 * 32 + nt * 8 + tig * 2;
            float o0 = fast_tanh(acc[mt][nt][0] + sB2[c0]);
            float o1 = fast_tanh(acc[mt][nt][1] + sB2[c0 + 1]);
            float o2 = fast_tanh(acc[mt][nt][2] + sB2[c0]);
            float o3 = fast_tanh(acc[mt][nt][3] + sB2[c0 + 1]);
            float w00 = sW3[2 * c0],     w01 = sW3[2 * c0 + 1];
            float w10 = sW3[2 * c0 + 2], w11 = sW3[2 * c0 + 3];
            e[mt][0][0] = fmaf(o0, w00, fmaf(o1, w10, e[mt][0][0]));
            e[mt][0][1] = fmaf(o0, w01, fmaf(o1, w11, e[mt][0][1]));
            e[mt][1][0] = fmaf(o2, w00, fmaf(o3, w10, e[mt][1][0]));
            e[mt][1][1] = fmaf(o2, w01, fmaf(o3, w11, e[mt][1][1]));
        }
    #pragma unroll
    for (int off = 1; off <= 2; off <<= 1)
        #pragma unroll
        for (int mt = 0; mt < 2; mt++)
            #pragma unroll
            for (int hh = 0; hh < 2; hh++) {
                e[mt][hh][0] += __shfl_xor_sync(0xffffffffu, e[mt][hh][0], off);
                e[mt][hh][1] += __shfl_xor_sync(0xffffffffu, e[mt][hh][1], off);
            }
    if (tig == 0) {
        #pragma unroll
        for (int mt = 0; mt < 2; mt++)
            #pragma unroll
            for (int hh = 0; hh < 2; hh++) {
                int row = mt * 16 + g + hh * 8;
                sRed[wn2 * 64 + row * 2 + 0] = e[mt][hh][0];
                sRed[wn2 * 64 + row * 2 + 1] = e[mt][hh][1];
            }
    }
    __syncthreads();

    if (tid < 64) {
        int row  = tid >> 1;
        int comp = tid & 1;
        float s = b3[comp];
        #pragma unroll
        for (int w = 0; w < 8; w++)
            s += sRed[w * 64 + row * 2 + comp];
        int rg = r0 + row;
        out[(size_t)(rg >> 8) * 512 + (size_t)(rg & 255) * 2 + comp] = s;
    }
}

extern "C" void kernel_launch(void* const* d_in, const int* in_sizes, int n_in,
                              void* d_out, int out_size) {
    const float* last = (const float*)d_in[0];
    const float* h    = (const float*)d_in[1];
    const float* We   = (const float*)d_in[2];
    const float* be   = (const float*)d_in[3];
    const float* W1   = (const float*)d_in[4];
    const float* b1   = (const float*)d_in[5];
    const float* W2   = (const float*)d_in[6];
    const float* b2   = (const float*)d_in[7];
    const float* W3   = (const float*)d_in[8];
    const float* b3   = (const float*)d_in[9];
    float* out = (float*)d_out;

    prep_weights<<<512, 256>>>(W1, W2);

    cudaFuncSetAttribute(fused_hmma_kernel,
                         cudaFuncAttributeMaxDynamicSharedMemorySize, SM_TOTAL);
    fused_hmma_kernel<<<NCTA, NTHREADS, SM_TOTAL>>>(last, h, We, be, b1, b2, W3, b3, out);
}

// round 17
// speedup vs baseline: 2.1201x; 2.1201x over previous
#include <cuda_runtime.h>
#include <cuda_bf16.h>
#include <stdint.h>
#include <math.h>

// ---------- problem constants ----------
#define NROWS    131072           // 512 graphs * 256 nodes
#define INDIM    128
#define HIDN     128
#define D2       256
#define MTILE    64               // rows per CTA = two 32-row sub-tiles
#define NCTA     (NROWS / MTILE)  // 2048
#define NTHREADS 256              // 8 warps, each covers 32 cols x both sub-tiles

// ---------- smem layout (bytes) ----------
// A: sub-tile t at t*32768 (hi 16KB | lo 16KB), t in {0,1}
#define SM_A     0                // 64KB total
#define SM_BW    65536            // per-warp B rings: 8 warps x 4KB (2 slots x (hi 1KB | lo 1KB))
#define SM_EMB   98304            // 128 f32
#define SM_B1    98816            // 256 f32
#define SM_B2    99840            // 256 f32
#define SM_W3    100864           // 512 f32
#define SM_RED   102912           // 8*64*2 f32 = 4KB
#define SM_TOTAL 107008           // <= 113664 for 2 CTAs/SM

// B fragments in global scratch, coalesced layout (same as R7..R15):
// u32 idx = ((((l*2+p)*16 + ks)*4 + wn)*4 + q)*128 + lane*4 + j
__device__ uint32_t g_Bf[131072];   // 512KB

static __device__ __forceinline__ uint32_t pack_bf(__nv_bfloat16 a, __nv_bfloat16 b) {
    return ((uint32_t)__bfloat16_as_ushort(b) << 16) | (uint32_t)__bfloat16_as_ushort(a);
}
static __device__ __forceinline__ void split_bf(float v, __nv_bfloat16& hi, __nv_bfloat16& lo) {
    hi = __float2bfloat16(v);
    lo = __float2bfloat16(v - __bfloat162float(hi));
}
static __device__ __forceinline__ uint32_t s2u(const void* p) {
    uint32_t a;
    asm("{ .reg .u64 t; cvta.to.shared.u64 t, %1; cvt.u32.u64 %0, t; }"
        : "=r"(a) : "l"(p));
    return a;
}
// fast accurate tanh: 1 - 2/(2^(x*2*log2e) + 1); MUFU.EX2 + MUFU.RCP
static __device__ __forceinline__ float fast_tanh(float x) {
    float e, r;
    asm("ex2.approx.f32 %0, %1;" : "=f"(e) : "f"(x * 2.8853900817779268f));
    asm("rcp.approx.f32 %0, %1;" : "=f"(r) : "f"(e + 1.0f));
    return fmaf(-2.0f, r, 1.0f);
}
// truncation split: hi-pair via PRMT, lo-pair via rn(v - hi)
static __device__ __forceinline__ uint32_t pack_hi_trunc(float a, float b) {
    uint32_t r;
    asm("prmt.b32 %0, %1, %2, 0x7632;" : "=r"(r)
        : "r"(__float_as_uint(a)), "r"(__float_as_uint(b)));
    return r;
}
static __device__ __forceinline__ float trunc_hi(float v) {
    return __uint_as_float(__float_as_uint(v) & 0xffff0000u);
}
static __device__ __forceinline__ uint32_t pack_lo(float a, float b) {
    uint32_t r;
    float la = a - trunc_hi(a);
    float lb = b - trunc_hi(b);
    asm("cvt.rn.bf16x2.f32 %0, %1, %2;" : "=r"(r) : "f"(lb), "f"(la));
    return r;
}

// ---------- prep: split W1/W2 into bf16 hi/lo fragments (coalesced layout) ----------
__global__ void prep_weights(const float* __restrict__ W1, const float* __restrict__ W2) {
    int i = blockIdx.x * blockDim.x + threadIdx.x;   // 0..131071
    int j    = i & 3;
    int lane = (i >> 2) & 31;
    int q    = (i >> 7) & 3;
    int wn   = (i >> 9) & 3;
    int ks   = (i >> 11) & 15;
    int p    = (i >> 15) & 1;
    int l    = i >> 16;
    int s   = q * 4 + j;
    int nt  = s >> 1;
    int reg = s & 1;
    int NT  = wn * 8 + nt;
    const float* W = l ? W2 : W1;
    int k0 = ks * 16 + (lane & 3) * 2 + reg * 8;
    int n  = NT * 8 + (lane >> 2);
    float v0 = W[k0 * 256 + n];
    float v1 = W[(k0 + 1) * 256 + n];
    __nv_bfloat16 h0, l0, h1, l1;
    split_bf(v0, h0, l0);
    split_bf(v1, h1, l1);
    g_Bf[i] = (p == 0) ? pack_bf(h0, h1) : pack_bf(l0, l1);
}

// ---------- asm wrappers ----------
static __device__ __forceinline__ void mma_bf16(float* d, const uint32_t* a,
                                                uint32_t b0, uint32_t b1) {
    asm volatile(
        "mma.sync.aligned.m16n8k16.row.col.f32.bf16.bf16.f32 "
        "{%0,%1,%2,%3}, {%4,%5,%6,%7}, {%8,%9}, {%0,%1,%2,%3};"
        : "+f"(d[0]), "+f"(d[1]), "+f"(d[2]), "+f"(d[3])
        : "r"(a[0]), "r"(a[1]), "r"(a[2]), "r"(a[3]), "r"(b0), "r"(b1));
}
static __device__ __forceinline__ void ldsm4(uint32_t* r, uint32_t saddr) {
    asm volatile("ldmatrix.sync.aligned.m8n8.x4.shared.b16 {%0,%1,%2,%3}, [%4];"
                 : "=r"(r[0]), "=r"(r[1]), "=r"(r[2]), "=r"(r[3]) : "r"(saddr));
}
static __device__ __forceinline__ void lds128(uint4& v, uint32_t saddr) {
    asm volatile("ld.shared.v4.u32 {%0,%1,%2,%3}, [%4];"
                 : "=r"(v.x), "=r"(v.y), "=r"(v.z), "=r"(v.w) : "r"(saddr));
}
static __device__ __forceinline__ void cp16(uint32_t dst, const void* src) {
    asm volatile("cp.async.cg.shared.global [%0], [%1], 16;"
                 :: "r"(dst), "l"(src) : "memory");
}
#define CP_COMMIT() asm volatile("cp.async.commit_group;" ::: "memory")
#define CP_WAIT(n)  asm volatile("cp.async.wait_group %0;" :: "n"(n) : "memory")

// A smem byte offset for (row r 0..31, k) within one sub-tile; per-ks block = 1KB
static __device__ __forceinline__ uint32_t offA(int r, int k) {
    uint32_t c = (uint32_t)(k & 15);
    uint32_t cp = (c + (uint32_t)((r & 4) << 1)) & 15u;
    return ((uint32_t)(k >> 4) << 10) + ((uint32_t)r << 5) + (cp << 1);
}

// ---------- main fused kernel ----------
__global__ __launch_bounds__(NTHREADS, 2)
void fused_hmma_kernel(const float* __restrict__ last,
                       const float* __restrict__ h,
                       const float* __restrict__ We,
                       const float* __restrict__ be,
                       const float* __restrict__ b1,
                       const float* __restrict__ b2,
                       const float* __restrict__ W3,
                       const float* __restrict__ b3,
                       float* __restrict__ out) {
    extern __shared__ char sm[];
    const uint32_t smb = s2u(sm);
    const int tid  = threadIdx.x;
    const int lane = tid & 31;
    const int wn2  = tid >> 5;       // warp id = 32-col slice, 0..7
    const int r0   = blockIdx.x * MTILE;
    const int grp  = r0 >> 8;        // 64 | 256 -> single graph per CTA

    float* sEmb = (float*)(sm + SM_EMB);
    float* sB1  = (float*)(sm + SM_B1);
    float* sB2  = (float*)(sm + SM_B2);
    float* sW3  = (float*)(sm + SM_W3);
    float* sRed = (float*)(sm + SM_RED);

    // per-warp B ring: 2 slots x 2KB
    const uint32_t bufbase = smb + SM_BW + (uint32_t)wn2 * 4096 + (uint32_t)lane * 16;
    const uint32_t gwoff   = (uint32_t)wn2 * 256 + (uint32_t)lane * 4;   // u32 units

    // fetch global ks index ksg (0..31; layer = ksg>>4) into ring slot ksg&1
    auto fetchB = [&](int ksg) {
        const uint32_t* srcH = g_Bf + (uint32_t)(((ksg >> 4) * 32 + (ksg & 15)) * 2048) + gwoff;
        uint32_t dst = bufbase + (uint32_t)(ksg & 1) * 2048;
        cp16(dst,         srcH);
        cp16(dst + 512,   srcH + 128);
        cp16(dst + 1024,  srcH + 32768);        // lo part (p=1)
        cp16(dst + 1536,  srcH + 32768 + 128);
        CP_COMMIT();
    };

    // ---- prologue: 2-deep per-warp prefetch, overlaps A build ----
    fetchB(0); fetchB(1);

    sB1[tid] = b1[tid];
    sB2[tid] = b2[tid];
    sW3[tid]       = W3[tid];
    sW3[tid + 256] = W3[tid + 256];

    if (tid < HIDN) {
        float acc0 = be[tid];
        const float* lrow = last + (size_t)grp * INDIM;
        #pragma unroll 4
        for (int k = 0; k < INDIM; k++)
            acc0 = fmaf(lrow[k], We[k * HIDN + tid], acc0);
        sEmb[tid] = acc0;
    }

    // A tiles, h half: 64 rows x 128 k (8 iters/thread)
    #pragma unroll
    for (int it = 0; it < 8; it++) {
        int idx = tid + it * NTHREADS;
        int r = idx >> 5, kq = idx & 31, k = kq * 4;
        float4 v = *(const float4*)(h + (size_t)(r0 + r) * HIDN + k);
        uint32_t off = (uint32_t)(r >> 5) * 32768 + offA(r & 31, k);
        *(uint2*)(sm + SM_A + off)         = make_uint2(pack_hi_trunc(v.x, v.y), pack_hi_trunc(v.z, v.w));
        *(uint2*)(sm + SM_A + off + 16384) = make_uint2(pack_lo(v.x, v.y),       pack_lo(v.z, v.w));
    }
    __syncthreads();   // sEmb ready

    // A tiles, embed half: k 128..255, broadcast across rows
    #pragma unroll
    for (int it = 0; it < 8; it++) {
        int idx = tid + it * NTHREADS;
        int r = idx >> 5, kq = idx & 31, k = 128 + kq * 4;
        float4 v = *(const float4*)(sEmb + kq * 4);
        uint32_t off = (uint32_t)(r >> 5) * 32768 + offA(r & 31, k);
        *(uint2*)(sm + SM_A + off)         = make_uint2(pack_hi_trunc(v.x, v.y), pack_hi_trunc(v.z, v.w));
        *(uint2*)(sm + SM_A + off + 16384) = make_uint2(pack_lo(v.x, v.y),       pack_lo(v.z, v.w));
    }
    __syncthreads();   // A tiles complete before any warp's mainloop reads

    const int g   = lane >> 2;
    const int tig = lane & 3;

    // per-lane ldmatrix offset within a 16-row block
    uint32_t laneoff;
    {
        int q = lane >> 3, rr = lane & 7;
        laneoff = (uint32_t)(((q & 1) * 8 + rr) * 32 +
                             ((((q >> 1) ^ (rr >> 2)) & 1) << 4));
    }
    const uint32_t abm0 = laneoff;          // rows 0..15 of a sub-tile
    const uint32_t abm1 = 512 + laneoff;    // rows 16..31

    float acc0[2][4][4];   // sub-tile 0: [mt][nt][c]
    float acc1[2][4][4];   // sub-tile 1

    // ---- barrier-free mainloop: 32 global ks (layer = ksg>>4) ----
    #pragma unroll 1
    for (int ksg = 0; ksg < 32; ksg++) {
        if ((ksg & 15) == 0) {
            #pragma unroll
            for (int mt = 0; mt < 2; mt++)
                #pragma unroll
                for (int nt = 0; nt < 4; nt++)
                    #pragma unroll
                    for (int c = 0; c < 4; c++) {
                        acc0[mt][nt][c] = 0.f;
                        acc1[mt][nt][c] = 0.f;
                    }
        }

        if (ksg < 31) { CP_WAIT(1); } else { CP_WAIT(0); }

        // B fragments (shared by both sub-tiles)
        union { uint4 q[2]; uint32_t b[8]; } BH, BL;
        {
            uint32_t bb = bufbase + (uint32_t)(ksg & 1) * 2048;
            lds128(BH.q[0], bb);
            lds128(BH.q[1], bb + 512);
            lds128(BL.q[0], bb + 1024);
            lds128(BL.q[1], bb + 1536);
        }

        const uint32_t abase = smb + SM_A + ((uint32_t)(ksg & 15) << 10);

        // ---- sub-tile 0 ----
        {
            uint32_t aH[2][4], aL[2][4];
            ldsm4(aH[0], abase + abm0);
            ldsm4(aH[1], abase + abm1);
            ldsm4(aL[0], abase + 16384 + abm0);
            ldsm4(aL[1], abase + 16384 + abm1);
            #pragma unroll
            for (int mt = 0; mt < 2; mt++)
                #pragma unroll
                for (int nt = 0; nt < 4; nt++)
                    mma_bf16(acc0[mt][nt], aH[mt], BH.b[nt * 2], BH.b[nt * 2 + 1]);
            #pragma unroll
            for (int mt = 0; mt < 2; mt++)
                #pragma unroll
                for (int nt = 0; nt < 4; nt++)
                    mma_bf16(acc0[mt][nt], aH[mt], BL.b[nt * 2], BL.b[nt * 2 + 1]);
            #pragma unroll
            for (int mt = 0; mt < 2; mt++)
                #pragma unroll
                for (int nt = 0; nt < 4; nt++)
                    mma_bf16(acc0[mt][nt], aL[mt], BH.b[nt * 2], BH.b[nt * 2 + 1]);
        }
        // ---- sub-tile 1 ----
        {
            uint32_t aH[2][4], aL[2][4];
            ldsm4(aH[0], abase + 32768 + abm0);
            ldsm4(aH[1], abase + 32768 + abm1);
            ldsm4(aL[0], abase + 32768 + 16384 + abm0);
            ldsm4(aL[1], abase + 32768 + 16384 + abm1);
            #pragma unroll
            for (int mt = 0; mt < 2; mt++)
                #pragma unroll
                for (int nt = 0; nt < 4; nt++)
                    mma_bf16(acc1[mt][nt], aH[mt], BH.b[nt * 2], BH.b[nt * 2 + 1]);
            #pragma unroll
            for (int mt = 0; mt < 2; mt++)
                #pragma unroll
                for (int nt = 0; nt < 4; nt++)
                    mma_bf16(acc1[mt][nt], aH[mt], BL.b[nt * 2], BL.b[nt * 2 + 1]);
            #pragma unroll
            for (int mt = 0; mt < 2; mt++)
                #pragma unroll
                for (int nt = 0; nt < 4; nt++)
                    mma_bf16(acc1[mt][nt], aL[mt], BH.b[nt * 2], BH.b[nt * 2 + 1]);
        }

        // refill ring slot (ksg&1) for ksg+2 — safe: the MMAs above already
        // consumed this slot's data (issue order enforces LDS completion)
        if (ksg <= 29) fetchB(ksg + 2);

        if (ksg == 15) {
            // ===== layer boundary: the ONLY CTA barriers in the mainloop =====
            __syncthreads();   // all warps done reading layer-1 A
            #pragma unroll
            for (int t = 0; t < 2; t++) {
                uint32_t tb = (uint32_t)t * 32768;
                #pragma unroll
                for (int mt = 0; mt < 2; mt++) {
                    int rA = mt * 16 + g;
                    int rB = rA + 8;
                    #pragma unroll
                    for (int nt = 0; nt < 4; nt++) {
                        float* a = t ? acc1[mt][nt] : acc0[mt][nt];
                        int c0 = wn2 * 32 + nt * 8 + tig * 2;
                        float t0 = fast_tanh(a[0] + sB1[c0]);
                        float t1 = fast_tanh(a[1] + sB1[c0 + 1]);
                        float t2 = fast_tanh(a[2] + sB1[c0]);
                        float t3 = fast_tanh(a[3] + sB1[c0 + 1]);
                        uint32_t oA = tb + offA(rA, c0);
                        *(uint32_t*)(sm + SM_A + oA)         = pack_hi_trunc(t0, t1);
                        *(uint32_t*)(sm + SM_A + oA + 16384) = pack_lo(t0, t1);
                        uint32_t oB = tb + offA(rB, c0);
                        *(uint32_t*)(sm + SM_A + oB)         = pack_hi_trunc(t2, t3);
                        *(uint32_t*)(sm + SM_A + oB + 16384) = pack_lo(t2, t3);
                    }
                }
            }
            __syncthreads();   // layer-2 A visible to all warps
        }
    }

    // ===== epilogue 2: tanh(+b2), dot with W3, reduce =====
    #pragma unroll
    for (int t = 0; t < 2; t++) {
        float e[2][2][2];   // [mt][rowhalf][comp]
        #pragma unroll
        for (int mt = 0; mt < 2; mt++)
            #pragma unroll
            for (int hh = 0; hh < 2; hh++) { e[mt][hh][0] = 0.f; e[mt][hh][1] = 0.f; }

        #pragma unroll
        for (int mt = 0; mt < 2; mt++)
            #pragma unroll
            for (int nt = 0; nt < 4; nt++) {
                const float* a = t ? acc1[mt][nt] : acc0[mt][nt];
                int c0 = wn2 * 32 + nt * 8 + tig * 2;
                float o0 = fast_tanh(a[0] + sB2[c0]);
                float o1 = fast_tanh(a[1] + sB2[c0 + 1]);
                float o2 = fast_tanh(a[2] + sB2[c0]);
                float o3 = fast_tanh(a[3] + sB2[c0 + 1]);
                float w00 = sW3[2 * c0],     w01 = sW3[2 * c0 + 1];
                float w10 = sW3[2 * c0 + 2], w11 = sW3[2 * c0 + 3];
                e[mt][0][0] = fmaf(o0, w00, fmaf(o1, w10, e[mt][0][0]));
                e[mt][0][1] = fmaf(o0, w01, fmaf(o1, w11, e[mt][0][1]));
                e[mt][1][0] = fmaf(o2, w00, fmaf(o3, w10, e[mt][1][0]));
                e[mt][1][1] = fmaf(o2, w01, fmaf(o3, w11, e[mt][1][1]));
            }
        #pragma unroll
        for (int off = 1; off <= 2; off <<= 1)
            #pragma unroll
            for (int mt = 0; mt < 2; mt++)
                #pragma unroll
                for (int hh = 0; hh < 2; hh++) {
                    e[mt][hh][0] += __shfl_xor_sync(0xffffffffu, e[mt][hh][0], off);
                    e[mt][hh][1] += __shfl_xor_sync(0xffffffffu, e[mt][hh][1], off);
                }
        if (tig == 0) {
            #pragma unroll
            for (int mt = 0; mt < 2; mt++)
                #pragma unroll
                for (int hh = 0; hh < 2; hh++) {
                    int row = t * 32 + mt * 16 + g + hh * 8;
                    sRed[wn2 * 128 + row * 2 + 0] = e[mt][hh][0];
                    sRed[wn2 * 128 + row * 2 + 1] = e[mt][hh][1];
                }
        }
    }
    __syncthreads();

    if (tid < 128) {
        int row  = tid >> 1;
        int comp = tid & 1;
        float s = b3[comp];
        #pragma unroll
        for (int w = 0; w < 8; w++)
            s += sRed[w * 128 + row * 2 + comp];
        int rg = r0 + row;
        out[(size_t)(rg >> 8) * 512 + (size_t)(rg & 255) * 2 + comp] = s;
    }
}

extern "C" void kernel_launch(void* const* d_in, const int* in_sizes, int n_in,
                              void* d_out, int out_size) {
    const float* last = (const float*)d_in[0];
    const float* h    = (const float*)d_in[1];
    const float* We   = (const float*)d_in[2];
    const float* be   = (const float*)d_in[3];
    const float* W1   = (const float*)d_in[4];
    const float* b1   = (const float*)d_in[5];
    const float* W2   = (const float*)d_in[6];
    const float* b2   = (const float*)d_in[7];
    const float* W3   = (const float*)d_in[8];
    const float* b3   = (const float*)d_in[9];
    float* out = (float*)d_out;

    prep_weights<<<512, 256>>>(W1, W2);

    cudaFuncSetAttribute(fused_hmma_kernel,
                         cudaFuncAttributeMaxDynamicSharedMemorySize, SM_TOTAL);
    fused_hmma_kernel<<<NCTA, NTHREADS, SM_TOTAL>>>(last, h, We, be, b1, b2, W3, b3, out);
}